// round 2
// baseline (speedup 1.0000x reference)
#include <cuda_runtime.h>
#include <cuda_bf16.h>
#include <cstdint>

// Problem constants (fixed by the dataset)
#define NN 100000
#define EE 3200000
#define IN_C 128
#define HID_C 256
#define OUT_C 64

// ---------------- static device scratch (allocation-free rule) ----------------
static __device__ float g_deg[NN];
static __device__ float g_dinv[NN];
static __device__ int   g_cnt[NN];
static __device__ int   g_off[NN + 1];
static __device__ int   g_cur[NN];
static __device__ int   g_cols[EE];
static __device__ float g_w[EE];
static __device__ __align__(16) float g_tx1[(size_t)NN * 256];
static __device__ __align__(16) float g_tmp[(size_t)NN * 256];
static __device__ __align__(16) float g_h[(size_t)NN * 256];

// ---------------- preprocessing ----------------
__global__ void init_kernel() {
    int i = blockIdx.x * blockDim.x + threadIdx.x;
    if (i < NN) { g_deg[i] = 0.f; g_cnt[i] = 0; }
}

// edge_index is int32 (JAX x64 disabled: jnp.int64 request silently -> int32).
__global__ void hist_kernel(const int* __restrict__ row,
                            const float* __restrict__ ew) {
    int e = blockIdx.x * blockDim.x + threadIdx.x;
    if (e >= EE) return;
    int r = row[e];
    atomicAdd(&g_cnt[r], 1);
    atomicAdd(&g_deg[r], ew[e]);
}

__global__ void dinv_kernel() {
    int i = blockIdx.x * blockDim.x + threadIdx.x;
    if (i >= NN) return;
    float d = g_deg[i];
    g_dinv[i] = (d > 0.f) ? rsqrtf(d) : 0.f;
}

// Single-block exclusive scan of g_cnt -> g_off / g_cur. 1024 threads,
// each owns a contiguous chunk of ceil(NN/1024)=98 elements.
__global__ void scan_kernel() {
    __shared__ int sm[1024];
    const int CH = (NN + 1023) / 1024;
    int t = threadIdx.x;
    int base = t * CH;
    int s = 0;
    for (int i = 0; i < CH; i++) {
        int idx = base + i;
        if (idx < NN) s += g_cnt[idx];
    }
    sm[t] = s;
    __syncthreads();
    for (int off = 1; off < 1024; off <<= 1) {
        int v = (t >= off) ? sm[t - off] : 0;
        __syncthreads();
        sm[t] += v;
        __syncthreads();
    }
    int run = sm[t] - s;  // exclusive prefix
    for (int i = 0; i < CH; i++) {
        int idx = base + i;
        if (idx < NN) {
            g_off[idx] = run;
            g_cur[idx] = run;
            run += g_cnt[idx];
        }
    }
    if (t == 1023) g_off[NN] = sm[1023];
}

__global__ void scatter_kernel(const int* __restrict__ ei,
                               const float* __restrict__ ew) {
    int e = blockIdx.x * blockDim.x + threadIdx.x;
    if (e >= EE) return;
    int r = ei[e];
    int c = ei[EE + e];
    int pos = atomicAdd(&g_cur[r], 1);
    g_cols[pos] = c;
    g_w[pos] = -g_dinv[r] * ew[e] * g_dinv[c];
}

// ---------------- SpMM: y[r,:] = sum_j w_j * x[col_j,:] (gather, no atomics)
// One warp per row. C=128 -> 1 float4/lane, C=256 -> 2 float4/lane.
template <int C>
__global__ __launch_bounds__(256) void spmm_kernel(const float* __restrict__ x,
                                                   float* __restrict__ y) {
    int warp = (blockIdx.x * blockDim.x + threadIdx.x) >> 5;
    int lane = threadIdx.x & 31;
    if (warp >= NN) return;
    constexpr int V = C / 128;
    int start = g_off[warp], end = g_off[warp + 1];
    float4 acc[V];
#pragma unroll
    for (int v = 0; v < V; v++) acc[v] = make_float4(0.f, 0.f, 0.f, 0.f);

    for (int j = start; j < end; j += 32) {
        int c = 0;
        float w = 0.f;
        if (j + lane < end) { c = g_cols[j + lane]; w = g_w[j + lane]; }
#pragma unroll 8
        for (int t = 0; t < 32; t++) {
            if (j + t >= end) break;
            int cc = __shfl_sync(0xffffffffu, c, t);
            float ww = __shfl_sync(0xffffffffu, w, t);
            const float4* xr = (const float4*)(x + (size_t)cc * C);
#pragma unroll
            for (int v = 0; v < V; v++) {
                float4 xv = __ldg(&xr[lane + 32 * v]);
                acc[v].x += ww * xv.x;
                acc[v].y += ww * xv.y;
                acc[v].z += ww * xv.z;
                acc[v].w += ww * xv.w;
            }
        }
    }
    float4* yr = (float4*)(y + (size_t)warp * C);
#pragma unroll
    for (int v = 0; v < V; v++) yr[lane + 32 * v] = acc[v];
}

// ---------------- fused 3-term GEMM ----------------
// out[m,n] = sum_seg sum_k A_seg[m,k] * W[seg,k,n] (+bias, optional relu)
// A_0 = A0, A_1 = A1, A_2 = 2*Atmp - A0  (Tx2 folded into the load)
// BM=BN=64, BK=16, 256 threads, 4x4 register tiles.
template <int CIN, int COUT, bool RELU>
__global__ __launch_bounds__(256) void gemm3_kernel(
    const float* __restrict__ A0, const float* __restrict__ A1,
    const float* __restrict__ Atmp, const float* __restrict__ Wt,
    const float* __restrict__ bias, float* __restrict__ out) {
    constexpr int BM = 64, BN = 64, BK = 16;
    __shared__ float As[BK][BM];
    __shared__ float Bs[BK][BN];

    int t = threadIdx.x;
    int tx = t & 15, ty = t >> 4;
    int m0 = blockIdx.x * BM;
    int n0 = blockIdx.y * BN;

    int arow = t >> 2, akq = t & 3;   // A loads: 64 rows x 4 float4
    int bk = t >> 4, bnq = t & 15;    // B loads: 16 k x 16 float4

    float acc[4][4];
#pragma unroll
    for (int i = 0; i < 4; i++)
#pragma unroll
        for (int j = 0; j < 4; j++) acc[i][j] = 0.f;

    for (int kb = 0; kb < 3 * CIN; kb += BK) {
        int seg = kb / CIN;
        int kl = kb % CIN;

        // --- load A tile (transposed into As[k][m]) ---
        float4 av = make_float4(0.f, 0.f, 0.f, 0.f);
        int gm = m0 + arow;
        if (gm < NN) {
            size_t base = (size_t)gm * CIN + kl + akq * 4;
            if (seg == 0) {
                av = __ldg((const float4*)(A0 + base));
            } else if (seg == 1) {
                av = __ldg((const float4*)(A1 + base));
            } else {
                float4 tv = __ldg((const float4*)(Atmp + base));
                float4 x0 = __ldg((const float4*)(A0 + base));
                av = make_float4(2.f * tv.x - x0.x, 2.f * tv.y - x0.y,
                                 2.f * tv.z - x0.z, 2.f * tv.w - x0.w);
            }
        }
        As[akq * 4 + 0][arow] = av.x;
        As[akq * 4 + 1][arow] = av.y;
        As[akq * 4 + 2][arow] = av.z;
        As[akq * 4 + 3][arow] = av.w;

        // --- load B tile ---
        float4 bv = __ldg((const float4*)(Wt + ((size_t)seg * CIN + kl + bk) * COUT +
                                          n0 + bnq * 4));
        *(float4*)&Bs[bk][bnq * 4] = bv;
        __syncthreads();

#pragma unroll
        for (int kk = 0; kk < BK; kk++) {
            float4 a4 = *(const float4*)&As[kk][ty * 4];
            float4 b4 = *(const float4*)&Bs[kk][tx * 4];
            float a[4] = {a4.x, a4.y, a4.z, a4.w};
            float b[4] = {b4.x, b4.y, b4.z, b4.w};
#pragma unroll
            for (int i = 0; i < 4; i++)
#pragma unroll
                for (int j = 0; j < 4; j++) acc[i][j] += a[i] * b[j];
        }
        __syncthreads();
    }

    float4 bb = __ldg((const float4*)(bias + n0 + tx * 4));
#pragma unroll
    for (int i = 0; i < 4; i++) {
        int gm = m0 + ty * 4 + i;
        if (gm < NN) {
            float4 r;
            r.x = acc[i][0] + bb.x;
            r.y = acc[i][1] + bb.y;
            r.z = acc[i][2] + bb.z;
            r.w = acc[i][3] + bb.w;
            if (RELU) {
                r.x = fmaxf(r.x, 0.f); r.y = fmaxf(r.y, 0.f);
                r.z = fmaxf(r.z, 0.f); r.w = fmaxf(r.w, 0.f);
            }
            *(float4*)(out + (size_t)gm * COUT + n0 + tx * 4) = r;
        }
    }
}

// ---------------- launch ----------------
extern "C" void kernel_launch(void* const* d_in, const int* in_sizes, int n_in,
                              void* d_out, int out_size) {
    const float* x  = (const float*)d_in[0];
    const int*   ei = (const int*)d_in[1];   // int32 (JAX default x64-disabled)
    const float* ew = (const float*)d_in[2];
    const float* W1 = (const float*)d_in[3];
    const float* b1 = (const float*)d_in[4];
    const float* W2 = (const float*)d_in[5];
    const float* b2 = (const float*)d_in[6];
    float*       out = (float*)d_out;

    float *tx1, *tmp, *h;
    cudaGetSymbolAddress((void**)&tx1, g_tx1);
    cudaGetSymbolAddress((void**)&tmp, g_tmp);
    cudaGetSymbolAddress((void**)&h, g_h);

    const int TB = 256;
    // graph normalization + CSR build (every call; graph-capturable, no allocs)
    init_kernel<<<(NN + TB - 1) / TB, TB>>>();
    hist_kernel<<<(EE + TB - 1) / TB, TB>>>(ei, ew);
    dinv_kernel<<<(NN + TB - 1) / TB, TB>>>();
    scan_kernel<<<1, 1024>>>();
    scatter_kernel<<<(EE + TB - 1) / TB, TB>>>(ei, ew);

    const int SPMM_BLOCKS = (NN * 32 + TB - 1) / TB;  // warp per row

    // ---- layer 1 (IN_C=128 -> HID_C=256, relu) ----
    spmm_kernel<128><<<SPMM_BLOCKS, TB>>>(x, tx1);       // Tx1 = L x
    spmm_kernel<128><<<SPMM_BLOCKS, TB>>>(tx1, tmp);     // tmp = L Tx1
    {
        dim3 grid((NN + 63) / 64, HID_C / 64);
        gemm3_kernel<128, HID_C, true><<<grid, 256>>>(x, tx1, tmp, W1, b1, h);
    }

    // ---- layer 2 (HID_C=256 -> OUT_C=64) ----
    spmm_kernel<256><<<SPMM_BLOCKS, TB>>>(h, tx1);       // Tx1' = L h
    spmm_kernel<256><<<SPMM_BLOCKS, TB>>>(tx1, tmp);     // tmp = L Tx1'
    {
        dim3 grid((NN + 63) / 64, OUT_C / 64);
        gemm3_kernel<256, OUT_C, false><<<grid, 256>>>(h, tx1, tmp, W2, b2, out);
    }
}

// round 4
// speedup vs baseline: 1.1167x; 1.1167x over previous
#include <cuda_runtime.h>
#include <cuda_bf16.h>
#include <cstdint>

// Problem constants (fixed by the dataset)
#define NN 100000
#define EE 3200000
#define IN_C 128
#define HID_C 256
#define OUT_C 64

// ---------------- static device scratch (allocation-free rule) ----------------
static __device__ float g_deg[NN];
static __device__ float g_dinv[NN];
static __device__ int   g_cnt[NN];
static __device__ int   g_start[NN];
static __device__ int   g_end[NN];
static __device__ int   g_cur[NN];
static __device__ int   g_total;
static __device__ int   g_cols[EE];
static __device__ float g_w[EE];
static __device__ __align__(16) float g_tx1[(size_t)NN * 256];
static __device__ __align__(16) float g_tmp[(size_t)NN * 256];
static __device__ __align__(16) float g_h[(size_t)NN * 256];

// ---------------- packed fp32x2 helpers (sm_100+) ----------------
__device__ __forceinline__ void ffma2(unsigned long long& d, unsigned long long a,
                                      unsigned long long b) {
    asm("fma.rn.f32x2 %0, %1, %2, %3;" : "=l"(d) : "l"(a), "l"(b), "l"(d));
}
__device__ __forceinline__ unsigned long long bcast2(float v) {
    unsigned long long r;
    asm("mov.b64 %0, {%1, %1};" : "=l"(r) : "f"(v));
    return r;
}
__device__ __forceinline__ void unpack2(unsigned long long p, float& lo, float& hi) {
    asm("mov.b64 {%0, %1}, %2;" : "=f"(lo), "=f"(hi) : "l"(p));
}

// ---------------- preprocessing ----------------
__global__ void init_kernel() {
    int i = blockIdx.x * blockDim.x + threadIdx.x;
    if (i < NN) { g_deg[i] = 0.f; g_cnt[i] = 0; }
    if (i == 0) g_total = 0;
}

// edge_index is int32 (JAX x64 disabled: jnp.int64 silently -> int32).
__global__ void hist_kernel(const int* __restrict__ row,
                            const float* __restrict__ ew) {
    int e = blockIdx.x * blockDim.x + threadIdx.x;
    if (e >= EE) return;
    int r = row[e];
    atomicAdd(&g_cnt[r], 1);
    atomicAdd(&g_deg[r], ew[e]);
}

// dinv + CSR segment allocation (no ordered scan needed: row order within the
// edge array is irrelevant for the gather SpMM; each row grabs a chunk).
__global__ void offsets_kernel() {
    int i = blockIdx.x * blockDim.x + threadIdx.x;
    if (i >= NN) return;
    float d = g_deg[i];
    g_dinv[i] = (d > 0.f) ? rsqrtf(d) : 0.f;
    int c = g_cnt[i];
    int pos = atomicAdd(&g_total, c);
    g_start[i] = pos;
    g_cur[i] = pos;
    g_end[i] = pos + c;
}

__global__ void scatter_kernel(const int* __restrict__ ei,
                               const float* __restrict__ ew) {
    int e = blockIdx.x * blockDim.x + threadIdx.x;
    if (e >= EE) return;
    int r = ei[e];
    int c = ei[EE + e];
    int pos = atomicAdd(&g_cur[r], 1);
    g_cols[pos] = c;
    g_w[pos] = -g_dinv[r] * ew[e] * g_dinv[c];
}

// ---------------- SpMM: y[r,:] = sum_j w_j * x[col_j,:] (gather, no atomics)
// One warp per row. C=128 -> 1 float4/lane, C=256 -> 2 float4/lane.
template <int C>
__global__ __launch_bounds__(256) void spmm_kernel(const float* __restrict__ x,
                                                   float* __restrict__ y) {
    int warp = (blockIdx.x * blockDim.x + threadIdx.x) >> 5;
    int lane = threadIdx.x & 31;
    if (warp >= NN) return;
    constexpr int V = C / 128;
    int start = g_start[warp], end = g_end[warp];
    float4 acc[V];
#pragma unroll
    for (int v = 0; v < V; v++) acc[v] = make_float4(0.f, 0.f, 0.f, 0.f);

    int nfull = (end - start) & ~31;
    int jfull = start + nfull;

    // fast path: full 32-edge chunks, branchless inner loop
    for (int j = start; j < jfull; j += 32) {
        int c = g_cols[j + lane];
        float w = g_w[j + lane];
#pragma unroll 8
        for (int t = 0; t < 32; t++) {
            int cc = __shfl_sync(0xffffffffu, c, t);
            float ww = __shfl_sync(0xffffffffu, w, t);
            const float4* xr = (const float4*)(x + (size_t)cc * C);
#pragma unroll
            for (int v = 0; v < V; v++) {
                float4 xv = __ldg(&xr[lane + 32 * v]);
                acc[v].x += ww * xv.x;
                acc[v].y += ww * xv.y;
                acc[v].z += ww * xv.z;
                acc[v].w += ww * xv.w;
            }
        }
    }
    // tail
    if (jfull < end) {
        int c = 0;
        float w = 0.f;
        if (jfull + lane < end) { c = g_cols[jfull + lane]; w = g_w[jfull + lane]; }
        int rem = end - jfull;
        for (int t = 0; t < rem; t++) {
            int cc = __shfl_sync(0xffffffffu, c, t);
            float ww = __shfl_sync(0xffffffffu, w, t);
            const float4* xr = (const float4*)(x + (size_t)cc * C);
#pragma unroll
            for (int v = 0; v < V; v++) {
                float4 xv = __ldg(&xr[lane + 32 * v]);
                acc[v].x += ww * xv.x;
                acc[v].y += ww * xv.y;
                acc[v].z += ww * xv.z;
                acc[v].w += ww * xv.w;
            }
        }
    }
    float4* yr = (float4*)(y + (size_t)warp * C);
#pragma unroll
    for (int v = 0; v < V; v++) yr[lane + 32 * v] = acc[v];
}

// ---------------- fused 3-term GEMM (packed f32x2 inner loop) ----------------
// out[m,n] = sum_seg sum_k A_seg[m,k] * W[seg,k,n] (+bias, optional relu)
// A_0 = A0, A_1 = A1, A_2 = 2*Atmp - A0  (Tx2 folded into the load)
// BM=BN=64, BK=16, 256 threads, 4x4 register tiles as 4x2 f32x2 pairs.
template <int CIN, int COUT, bool RELU>
__global__ __launch_bounds__(256) void gemm3_kernel(
    const float* __restrict__ A0, const float* __restrict__ A1,
    const float* __restrict__ Atmp, const float* __restrict__ Wt,
    const float* __restrict__ bias, float* __restrict__ out) {
    constexpr int BM = 64, BN = 64, BK = 16;
    __shared__ __align__(16) float As[BK][BM];
    __shared__ __align__(16) float Bs[BK][BN];

    int t = threadIdx.x;
    int tx = t & 15, ty = t >> 4;
    int m0 = blockIdx.x * BM;
    int n0 = blockIdx.y * BN;

    int arow = t >> 2, akq = t & 3;   // A loads: 64 rows x 4 float4
    int bk = t >> 4, bnq = t & 15;    // B loads: 16 k x 16 float4

    unsigned long long acc2[4][2];
#pragma unroll
    for (int i = 0; i < 4; i++)
#pragma unroll
        for (int j = 0; j < 2; j++) acc2[i][j] = 0ull;

    for (int kb = 0; kb < 3 * CIN; kb += BK) {
        int seg = kb / CIN;
        int kl = kb % CIN;

        // --- load A tile (transposed into As[k][m]) ---
        float4 av = make_float4(0.f, 0.f, 0.f, 0.f);
        int gm = m0 + arow;
        if (gm < NN) {
            size_t base = (size_t)gm * CIN + kl + akq * 4;
            if (seg == 0) {
                av = __ldg((const float4*)(A0 + base));
            } else if (seg == 1) {
                av = __ldg((const float4*)(A1 + base));
            } else {
                float4 tv = __ldg((const float4*)(Atmp + base));
                float4 x0 = __ldg((const float4*)(A0 + base));
                av = make_float4(2.f * tv.x - x0.x, 2.f * tv.y - x0.y,
                                 2.f * tv.z - x0.z, 2.f * tv.w - x0.w);
            }
        }
        As[akq * 4 + 0][arow] = av.x;
        As[akq * 4 + 1][arow] = av.y;
        As[akq * 4 + 2][arow] = av.z;
        As[akq * 4 + 3][arow] = av.w;

        // --- load B tile ---
        float4 bv = __ldg((const float4*)(Wt + ((size_t)seg * CIN + kl + bk) * COUT +
                                          n0 + bnq * 4));
        *(float4*)&Bs[bk][bnq * 4] = bv;
        __syncthreads();

#pragma unroll
        for (int kk = 0; kk < BK; kk++) {
            float4 a4 = *(const float4*)&As[kk][ty * 4];
            ulonglong2 b2 = *(const ulonglong2*)&Bs[kk][tx * 4];  // 2 f32x2 pairs
            unsigned long long ap[4];
            ap[0] = bcast2(a4.x);
            ap[1] = bcast2(a4.y);
            ap[2] = bcast2(a4.z);
            ap[3] = bcast2(a4.w);
#pragma unroll
            for (int i = 0; i < 4; i++) {
                ffma2(acc2[i][0], ap[i], b2.x);
                ffma2(acc2[i][1], ap[i], b2.y);
            }
        }
        __syncthreads();
    }

    float4 bb = __ldg((const float4*)(bias + n0 + tx * 4));
#pragma unroll
    for (int i = 0; i < 4; i++) {
        int gm = m0 + ty * 4 + i;
        if (gm < NN) {
            float4 r;
            unpack2(acc2[i][0], r.x, r.y);
            unpack2(acc2[i][1], r.z, r.w);
            r.x += bb.x; r.y += bb.y; r.z += bb.z; r.w += bb.w;
            if (RELU) {
                r.x = fmaxf(r.x, 0.f); r.y = fmaxf(r.y, 0.f);
                r.z = fmaxf(r.z, 0.f); r.w = fmaxf(r.w, 0.f);
            }
            *(float4*)(out + (size_t)gm * COUT + n0 + tx * 4) = r;
        }
    }
}

// ---------------- launch ----------------
extern "C" void kernel_launch(void* const* d_in, const int* in_sizes, int n_in,
                              void* d_out, int out_size) {
    const float* x  = (const float*)d_in[0];
    const int*   ei = (const int*)d_in[1];   // int32 (JAX default x64-disabled)
    const float* ew = (const float*)d_in[2];
    const float* W1 = (const float*)d_in[3];
    const float* b1 = (const float*)d_in[4];
    const float* W2 = (const float*)d_in[5];
    const float* b2 = (const float*)d_in[6];
    float*       out = (float*)d_out;

    float *tx1, *tmp, *h;
    cudaGetSymbolAddress((void**)&tx1, g_tx1);
    cudaGetSymbolAddress((void**)&tmp, g_tmp);
    cudaGetSymbolAddress((void**)&h, g_h);

    const int TB = 256;
    // graph normalization + CSR build (every call; graph-capturable, no allocs)
    init_kernel<<<(NN + TB - 1) / TB, TB>>>();
    hist_kernel<<<(EE + TB - 1) / TB, TB>>>(ei, ew);
    offsets_kernel<<<(NN + TB - 1) / TB, TB>>>();
    scatter_kernel<<<(EE + TB - 1) / TB, TB>>>(ei, ew);

    const int SPMM_BLOCKS = (NN * 32 + TB - 1) / TB;  // warp per row

    // ---- layer 1 (IN_C=128 -> HID_C=256, relu) ----
    spmm_kernel<128><<<SPMM_BLOCKS, TB>>>(x, tx1);       // Tx1 = L x
    spmm_kernel<128><<<SPMM_BLOCKS, TB>>>(tx1, tmp);     // tmp = L Tx1
    {
        dim3 grid((NN + 63) / 64, HID_C / 64);
        gemm3_kernel<128, HID_C, true><<<grid, 256>>>(x, tx1, tmp, W1, b1, h);
    }

    // ---- layer 2 (HID_C=256 -> OUT_C=64) ----
    spmm_kernel<256><<<SPMM_BLOCKS, TB>>>(h, tx1);       // Tx1' = L h
    spmm_kernel<256><<<SPMM_BLOCKS, TB>>>(tx1, tmp);     // tmp = L Tx1'
    {
        dim3 grid((NN + 63) / 64, OUT_C / 64);
        gemm3_kernel<256, OUT_C, false><<<grid, 256>>>(h, tx1, tmp, W2, b2, out);
    }
}

// round 5
// speedup vs baseline: 1.3687x; 1.2256x over previous
#include <cuda_runtime.h>
#include <cuda_bf16.h>
#include <cstdint>

// Problem constants (fixed by the dataset)
#define NN 100000
#define EE 3200000
#define IN_C 128
#define HID_C 256
#define OUT_C 64

// ---------------- static device scratch (allocation-free rule) ----------------
static __device__ float g_deg[NN];
static __device__ float g_dinv[NN];
static __device__ int   g_cnt[NN];
static __device__ int   g_start[NN];
static __device__ int   g_end[NN];
static __device__ int   g_cur[NN];
static __device__ int   g_total;
static __device__ int   g_cols[EE];
static __device__ float g_w[EE];
// g_tx1: layer1 Tx1 (N x 128), later S = [s1|s2] (N x 128)
// g_tmp: layer1 Tx2-src (N x 128), later P = [a|u|v] (N x 192)
// g_h:   h (N x 256)
static __device__ __align__(16) float g_tx1[(size_t)NN * 128];
static __device__ __align__(16) float g_tmp[(size_t)NN * 256];
static __device__ __align__(16) float g_h[(size_t)NN * 256];

// ---------------- packed fp32x2 helpers (sm_100+) ----------------
__device__ __forceinline__ void ffma2(unsigned long long& d, unsigned long long a,
                                      unsigned long long b) {
    asm("fma.rn.f32x2 %0, %1, %2, %3;" : "=l"(d) : "l"(a), "l"(b), "l"(d));
}
__device__ __forceinline__ unsigned long long bcast2(float v) {
    unsigned long long r;
    asm("mov.b64 %0, {%1, %1};" : "=l"(r) : "f"(v));
    return r;
}
__device__ __forceinline__ void unpack2(unsigned long long p, float& lo, float& hi) {
    asm("mov.b64 {%0, %1}, %2;" : "=f"(lo), "=f"(hi) : "l"(p));
}

// ---------------- preprocessing ----------------
__global__ void init_kernel() {
    int i = blockIdx.x * blockDim.x + threadIdx.x;
    if (i < NN) { g_deg[i] = 0.f; g_cnt[i] = 0; }
    if (i == 0) g_total = 0;
}

// edge_index is int32 (JAX x64 disabled: jnp.int64 silently -> int32).
__global__ void hist_kernel(const int* __restrict__ row,
                            const float* __restrict__ ew) {
    int e = blockIdx.x * blockDim.x + threadIdx.x;
    if (e >= EE) return;
    int r = row[e];
    atomicAdd(&g_cnt[r], 1);
    atomicAdd(&g_deg[r], ew[e]);
}

// dinv + CSR segment allocation (unordered chunk grab; row order irrelevant
// for the gather SpMM).
__global__ void offsets_kernel() {
    int i = blockIdx.x * blockDim.x + threadIdx.x;
    if (i >= NN) return;
    float d = g_deg[i];
    g_dinv[i] = (d > 0.f) ? rsqrtf(d) : 0.f;
    int c = g_cnt[i];
    int pos = atomicAdd(&g_total, c);
    g_start[i] = pos;
    g_cur[i] = pos;
    g_end[i] = pos + c;
}

__global__ void scatter_kernel(const int* __restrict__ ei,
                               const float* __restrict__ ew) {
    int e = blockIdx.x * blockDim.x + threadIdx.x;
    if (e >= EE) return;
    int r = ei[e];
    int c = ei[EE + e];
    int pos = atomicAdd(&g_cur[r], 1);
    g_cols[pos] = c;
    g_w[pos] = -g_dinv[r] * ew[e] * g_dinv[c];
}

// ---------------- SpMM: y[r,:] = sum_j w_j * src[col_j, SOFF:SOFF+C]
// One warp per row. C=128 -> 1 float4/lane. SSTRIDE/DSTRIDE in floats.
template <int C, int SSTRIDE, int SOFF, int DSTRIDE>
__global__ __launch_bounds__(256) void spmm_kernel(const float* __restrict__ x,
                                                   float* __restrict__ y) {
    int warp = (blockIdx.x * blockDim.x + threadIdx.x) >> 5;
    int lane = threadIdx.x & 31;
    if (warp >= NN) return;
    constexpr int V = C / 128;
    int start = g_start[warp], end = g_end[warp];
    float4 acc[V];
#pragma unroll
    for (int v = 0; v < V; v++) acc[v] = make_float4(0.f, 0.f, 0.f, 0.f);

    int jfull = start + ((end - start) & ~31);

    for (int j = start; j < jfull; j += 32) {
        int c = g_cols[j + lane];
        float w = g_w[j + lane];
#pragma unroll 8
        for (int t = 0; t < 32; t++) {
            int cc = __shfl_sync(0xffffffffu, c, t);
            float ww = __shfl_sync(0xffffffffu, w, t);
            const float4* xr = (const float4*)(x + (size_t)cc * SSTRIDE + SOFF);
#pragma unroll
            for (int v = 0; v < V; v++) {
                float4 xv = __ldg(&xr[lane + 32 * v]);
                acc[v].x += ww * xv.x;
                acc[v].y += ww * xv.y;
                acc[v].z += ww * xv.z;
                acc[v].w += ww * xv.w;
            }
        }
    }
    if (jfull < end) {
        int c = 0;
        float w = 0.f;
        if (jfull + lane < end) { c = g_cols[jfull + lane]; w = g_w[jfull + lane]; }
        int rem = end - jfull;
        for (int t = 0; t < rem; t++) {
            int cc = __shfl_sync(0xffffffffu, c, t);
            float ww = __shfl_sync(0xffffffffu, w, t);
            const float4* xr = (const float4*)(x + (size_t)cc * SSTRIDE + SOFF);
#pragma unroll
            for (int v = 0; v < V; v++) {
                float4 xv = __ldg(&xr[lane + 32 * v]);
                acc[v].x += ww * xv.x;
                acc[v].y += ww * xv.y;
                acc[v].z += ww * xv.z;
                acc[v].w += ww * xv.w;
            }
        }
    }
    float4* yr = (float4*)(y + (size_t)warp * DSTRIDE);
#pragma unroll
    for (int v = 0; v < V; v++) yr[lane + 32 * v] = acc[v];
}

// ---------------- final SpMM (C=64) with fused layer-2 epilogue ----------------
// acc = L s2  (gather S[c, 64:128]);  out[r] = a - v + s1 + 2*acc + b2
// P row: [a(0:64) | u(64:128) | v(128:192)], stride 192. S row: [s1|s2], stride 128.
__global__ __launch_bounds__(256) void spmm_final_kernel(
    const float* __restrict__ S, const float* __restrict__ P,
    const float* __restrict__ bias, float* __restrict__ out) {
    int warp = (blockIdx.x * blockDim.x + threadIdx.x) >> 5;
    int lane = threadIdx.x & 31;
    if (warp >= NN) return;
    int start = g_start[warp], end = g_end[warp];
    float2 acc = make_float2(0.f, 0.f);

    int jfull = start + ((end - start) & ~31);

    for (int j = start; j < jfull; j += 32) {
        int c = g_cols[j + lane];
        float w = g_w[j + lane];
#pragma unroll 8
        for (int t = 0; t < 32; t++) {
            int cc = __shfl_sync(0xffffffffu, c, t);
            float ww = __shfl_sync(0xffffffffu, w, t);
            float2 xv = __ldg((const float2*)(S + (size_t)cc * 128 + 64) + lane);
            acc.x += ww * xv.x;
            acc.y += ww * xv.y;
        }
    }
    if (jfull < end) {
        int c = 0;
        float w = 0.f;
        if (jfull + lane < end) { c = g_cols[jfull + lane]; w = g_w[jfull + lane]; }
        int rem = end - jfull;
        for (int t = 0; t < rem; t++) {
            int cc = __shfl_sync(0xffffffffu, c, t);
            float ww = __shfl_sync(0xffffffffu, w, t);
            float2 xv = __ldg((const float2*)(S + (size_t)cc * 128 + 64) + lane);
            acc.x += ww * xv.x;
            acc.y += ww * xv.y;
        }
    }
    // epilogue
    float2 a  = __ldg((const float2*)(P + (size_t)warp * 192) + lane);
    float2 v  = __ldg((const float2*)(P + (size_t)warp * 192 + 128) + lane);
    float2 s1 = __ldg((const float2*)(S + (size_t)warp * 128) + lane);
    float2 bb = __ldg((const float2*)bias + lane);
    float2 r;
    r.x = a.x - v.x + s1.x + 2.f * acc.x + bb.x;
    r.y = a.y - v.y + s1.y + 2.f * acc.y + bb.y;
    *((float2*)(out + (size_t)warp * 64) + lane) = r;
}

// ---------------- fused 3-term GEMM, layer 1 (packed f32x2) ----------------
// h[m,n] = relu(sum_seg sum_k A_seg[m,k] * W1[seg,k,n] + b1), A_2 = 2*Atmp - A0
template <int CIN, int COUT>
__global__ __launch_bounds__(256) void gemm3_kernel(
    const float* __restrict__ A0, const float* __restrict__ A1,
    const float* __restrict__ Atmp, const float* __restrict__ Wt,
    const float* __restrict__ bias, float* __restrict__ out) {
    constexpr int BM = 64, BN = 64, BK = 16;
    __shared__ __align__(16) float As[BK][BM];
    __shared__ __align__(16) float Bs[BK][BN];

    int t = threadIdx.x;
    int tx = t & 15, ty = t >> 4;
    int m0 = blockIdx.x * BM;
    int n0 = blockIdx.y * BN;

    int arow = t >> 2, akq = t & 3;
    int bk = t >> 4, bnq = t & 15;

    unsigned long long acc2[4][2];
#pragma unroll
    for (int i = 0; i < 4; i++)
#pragma unroll
        for (int j = 0; j < 2; j++) acc2[i][j] = 0ull;

    for (int kb = 0; kb < 3 * CIN; kb += BK) {
        int seg = kb / CIN;
        int kl = kb % CIN;

        float4 av = make_float4(0.f, 0.f, 0.f, 0.f);
        int gm = m0 + arow;
        if (gm < NN) {
            size_t base = (size_t)gm * CIN + kl + akq * 4;
            if (seg == 0) {
                av = __ldg((const float4*)(A0 + base));
            } else if (seg == 1) {
                av = __ldg((const float4*)(A1 + base));
            } else {
                float4 tv = __ldg((const float4*)(Atmp + base));
                float4 x0 = __ldg((const float4*)(A0 + base));
                av = make_float4(2.f * tv.x - x0.x, 2.f * tv.y - x0.y,
                                 2.f * tv.z - x0.z, 2.f * tv.w - x0.w);
            }
        }
        As[akq * 4 + 0][arow] = av.x;
        As[akq * 4 + 1][arow] = av.y;
        As[akq * 4 + 2][arow] = av.z;
        As[akq * 4 + 3][arow] = av.w;

        float4 bv = __ldg((const float4*)(Wt + ((size_t)seg * CIN + kl + bk) * COUT +
                                          n0 + bnq * 4));
        *(float4*)&Bs[bk][bnq * 4] = bv;
        __syncthreads();

#pragma unroll
        for (int kk = 0; kk < BK; kk++) {
            float4 a4 = *(const float4*)&As[kk][ty * 4];
            ulonglong2 b2 = *(const ulonglong2*)&Bs[kk][tx * 4];
            unsigned long long ap[4];
            ap[0] = bcast2(a4.x);
            ap[1] = bcast2(a4.y);
            ap[2] = bcast2(a4.z);
            ap[3] = bcast2(a4.w);
#pragma unroll
            for (int i = 0; i < 4; i++) {
                ffma2(acc2[i][0], ap[i], b2.x);
                ffma2(acc2[i][1], ap[i], b2.y);
            }
        }
        __syncthreads();
    }

    float4 bb = __ldg((const float4*)(bias + n0 + tx * 4));
#pragma unroll
    for (int i = 0; i < 4; i++) {
        int gm = m0 + ty * 4 + i;
        if (gm < NN) {
            float4 r;
            unpack2(acc2[i][0], r.x, r.y);
            unpack2(acc2[i][1], r.z, r.w);
            r.x = fmaxf(r.x + bb.x, 0.f);
            r.y = fmaxf(r.y + bb.y, 0.f);
            r.z = fmaxf(r.z + bb.z, 0.f);
            r.w = fmaxf(r.w + bb.w, 0.f);
            *(float4*)(out + (size_t)gm * COUT + n0 + tx * 4) = r;
        }
    }
}

// ---------------- layer-2 GEMM: P = h @ [W0|W1|W2]  (N x 192, no bias) -------
// grid.y = segment (0..2). P row stride 192; segment s occupies cols [64s, 64s+64).
__global__ __launch_bounds__(256) void gemm_l2_kernel(
    const float* __restrict__ A, const float* __restrict__ Wt,
    float* __restrict__ P) {
    constexpr int BM = 64, BN = 64, BK = 16, K = 256;
    __shared__ __align__(16) float As[BK][BM];
    __shared__ __align__(16) float Bs[BK][BN];

    int t = threadIdx.x;
    int tx = t & 15, ty = t >> 4;
    int m0 = blockIdx.x * BM;
    int seg = blockIdx.y;

    int arow = t >> 2, akq = t & 3;
    int bk = t >> 4, bnq = t & 15;

    unsigned long long acc2[4][2];
#pragma unroll
    for (int i = 0; i < 4; i++)
#pragma unroll
        for (int j = 0; j < 2; j++) acc2[i][j] = 0ull;

    const float* Wseg = Wt + (size_t)seg * K * 64;

    for (int kb = 0; kb < K; kb += BK) {
        float4 av = make_float4(0.f, 0.f, 0.f, 0.f);
        int gm = m0 + arow;
        if (gm < NN)
            av = __ldg((const float4*)(A + (size_t)gm * K + kb + akq * 4));
        As[akq * 4 + 0][arow] = av.x;
        As[akq * 4 + 1][arow] = av.y;
        As[akq * 4 + 2][arow] = av.z;
        As[akq * 4 + 3][arow] = av.w;

        float4 bv = __ldg((const float4*)(Wseg + (size_t)(kb + bk) * 64 + bnq * 4));
        *(float4*)&Bs[bk][bnq * 4] = bv;
        __syncthreads();

#pragma unroll
        for (int kk = 0; kk < BK; kk++) {
            float4 a4 = *(const float4*)&As[kk][ty * 4];
            ulonglong2 b2 = *(const ulonglong2*)&Bs[kk][tx * 4];
            unsigned long long ap[4];
            ap[0] = bcast2(a4.x);
            ap[1] = bcast2(a4.y);
            ap[2] = bcast2(a4.z);
            ap[3] = bcast2(a4.w);
#pragma unroll
            for (int i = 0; i < 4; i++) {
                ffma2(acc2[i][0], ap[i], b2.x);
                ffma2(acc2[i][1], ap[i], b2.y);
            }
        }
        __syncthreads();
    }

#pragma unroll
    for (int i = 0; i < 4; i++) {
        int gm = m0 + ty * 4 + i;
        if (gm < NN) {
            float4 r;
            unpack2(acc2[i][0], r.x, r.y);
            unpack2(acc2[i][1], r.z, r.w);
            *(float4*)(P + (size_t)gm * 192 + seg * 64 + tx * 4) = r;
        }
    }
}

// ---------------- launch ----------------
extern "C" void kernel_launch(void* const* d_in, const int* in_sizes, int n_in,
                              void* d_out, int out_size) {
    const float* x  = (const float*)d_in[0];
    const int*   ei = (const int*)d_in[1];   // int32 (JAX default x64-disabled)
    const float* ew = (const float*)d_in[2];
    const float* W1 = (const float*)d_in[3];
    const float* b1 = (const float*)d_in[4];
    const float* W2 = (const float*)d_in[5];
    const float* b2 = (const float*)d_in[6];
    float*       out = (float*)d_out;

    float *tx1, *tmp, *h;
    cudaGetSymbolAddress((void**)&tx1, g_tx1);
    cudaGetSymbolAddress((void**)&tmp, g_tmp);
    cudaGetSymbolAddress((void**)&h, g_h);

    const int TB = 256;
    // graph normalization + CSR build
    init_kernel<<<(NN + TB - 1) / TB, TB>>>();
    hist_kernel<<<(EE + TB - 1) / TB, TB>>>(ei, ew);
    offsets_kernel<<<(NN + TB - 1) / TB, TB>>>();
    scatter_kernel<<<(EE + TB - 1) / TB, TB>>>(ei, ew);

    const int SPMM_BLOCKS = (NN * 32 + TB - 1) / TB;  // warp per row

    // ---- layer 1 (input-space recurrence, C=128) ----
    spmm_kernel<128, 128, 0, 128><<<SPMM_BLOCKS, TB>>>(x, tx1);   // Tx1 = L x
    spmm_kernel<128, 128, 0, 128><<<SPMM_BLOCKS, TB>>>(tx1, tmp); // L Tx1
    {
        dim3 grid((NN + 63) / 64, HID_C / 64);
        gemm3_kernel<128, HID_C><<<grid, 256>>>(x, tx1, tmp, W1, b1, h);
    }

    // ---- layer 2 (output-space recurrence, C=64) ----
    // P = [a|u|v] = h @ [W2_0 | W2_1 | W2_2]   (N x 192)
    {
        dim3 grid((NN + 63) / 64, 3);
        gemm_l2_kernel<<<grid, 256>>>(h, W2, tmp);
    }
    // S = [s1|s2] = L [u|v]  (dual C=128 pass over P cols 64..192)
    spmm_kernel<128, 192, 64, 128><<<SPMM_BLOCKS, TB>>>(tmp, tx1);
    // out = a - v + s1 + 2*L(s2) + b2  (C=64 pass + fused epilogue)
    spmm_final_kernel<<<SPMM_BLOCKS, TB>>>(tx1, tmp, b2, out);
}